// round 13
// baseline (speedup 1.0000x reference)
#include <cuda_runtime.h>
#include <cstdint>

#define NB 8
#define NS 2048
#define NH 8
#define NDK 64
#define NDE 512

// ---------------- scratch (device globals; no allocations allowed) ----------
__device__ float g_qs[NB * NH * NS * NDK];   // 32 MB, pre-scaled by 1/8
__device__ float g_ks[NB * NH * NS * NDK];   // 32 MB
__device__ float g_vs[NB * NH * NS * NDK];   // 32 MB
__device__ float g_ctx[NB * NS * NDE];       // 32 MB
__device__ float g_rl[NB * NH * NS];         // 512 KB: 1/rowsum per (b,h,s)

// ---------------- fast exp: FFMA-pipe polynomial (MUFU is slow on sm_103a) --
__device__ __forceinline__ float fexp(float x) {
    float y = x * 1.4426950408889634f;          // log2(e)
    y = fminf(fmaxf(y, -120.0f), 120.0f);
    float t = y + 12582912.0f;                  // round-to-nearest-int trick
    float r = t - 12582912.0f;
    float f = y - r;                            // f in [-0.5, 0.5]
    int   ei = __float_as_int(t) - 0x4B400000;  // integer value of r
    float p = 1.3333558146e-3f;
    p = fmaf(p, f, 9.6181291076e-3f);
    p = fmaf(p, f, 5.5504108665e-2f);
    p = fmaf(p, f, 2.4022650696e-1f);
    p = fmaf(p, f, 6.9314718056e-1f);
    p = fmaf(p, f, 1.0f);
    return p * __int_as_float((ei + 127) << 23);
}

// ---------------- dummy: steers ncu's capture (-s 5 -c 1) onto k_qke --------
__global__ void k_dummy() {}

// ---------------- kernel 1: projections q_s/k_s/v_s = X @ Wq + bq -----------
__global__ __launch_bounds__(256) void k_proj(
    const float* __restrict__ Q, const float* __restrict__ K,
    const float* __restrict__ V, const float* __restrict__ W,
    const float* __restrict__ bias)
{
    const int which = blockIdx.z;
    const float* X = (which == 0) ? Q : (which == 1) ? K : V;
    float* O = (which == 0) ? g_qs : (which == 1) ? g_ks : g_vs;
    const float scl = (which == 0) ? 0.125f : 1.0f;

    __shared__ float As[16][64];   // [k][m] (transposed)
    __shared__ float Bs[16][64];   // [k][n]

    const int tid = threadIdx.x;
    const int tx = tid & 15, ty = tid >> 4;
    const int m0 = blockIdx.y * 64, n0 = blockIdx.x * 64;

    float acc[4][4] = {};

    for (int k0 = 0; k0 < NDE; k0 += 16) {
        {
            int r = tid >> 2;
            int c = (tid & 3) * 4;
            float4 a = *(const float4*)(X + (size_t)(m0 + r) * NDE + k0 + c);
            As[c + 0][r] = a.x; As[c + 1][r] = a.y;
            As[c + 2][r] = a.z; As[c + 3][r] = a.w;
        }
        {
            int r = tid >> 4;
            int c = (tid & 15) * 4;
            *(float4*)&Bs[r][c] = *(const float4*)(W + (size_t)(k0 + r) * NDE + n0 + c);
        }
        __syncthreads();
        #pragma unroll
        for (int kk = 0; kk < 16; kk++) {
            float4 a = *(const float4*)&As[kk][ty * 4];
            float4 b = *(const float4*)&Bs[kk][tx * 4];
            float av[4] = {a.x, a.y, a.z, a.w};
            float bv[4] = {b.x, b.y, b.z, b.w};
            #pragma unroll
            for (int i = 0; i < 4; i++)
                #pragma unroll
                for (int j = 0; j < 4; j++)
                    acc[i][j] = fmaf(av[i], bv[j], acc[i][j]);
        }
        __syncthreads();
    }

    const int hh = n0 >> 6;                  // whole tile is one head
    float4 bi = *(const float4*)(bias + n0 + tx * 4);
    #pragma unroll
    for (int i = 0; i < 4; i++) {
        int m = m0 + ty * 4 + i;
        int bb = m >> 11;
        int ss = m & 2047;
        float4 o;
        o.x = (acc[i][0] + bi.x) * scl;
        o.y = (acc[i][1] + bi.y) * scl;
        o.z = (acc[i][2] + bi.z) * scl;
        o.w = (acc[i][3] + bi.w) * scl;
        *(float4*)(O + ((size_t)(bb * NH + hh) * NS + ss) * NDK + tx * 4) = o;
    }
}

// ---------------- kernel 2a: QK + exp + unnormalized weight store + rowsums -
// (byte-identical body to R11 so this round's ncu profile attributes cleanly)
__global__ __launch_bounds__(256) void k_qke(
    const unsigned char* __restrict__ mask, float* __restrict__ wgt)
{
    extern __shared__ float sm[];
    float* Qs = sm;            // [64][128]  (d-major, transposed)
    float* Ks = sm + 8192;     // [64][64]   (d-major, transposed)
    float* ls = sm + 12288;    // [128]

    const int qt = blockIdx.x, h = blockIdx.y, b = blockIdx.z;
    const float* qsp = g_qs + (((size_t)(b * NH + h) * NS) + qt * 128) * NDK;
    const float* ksp = g_ks + ((size_t)(b * NH + h) * NS) * NDK;
    float* wrow = wgt + (((size_t)(b * NH + h) * NS) + qt * 128) * NS;
    const unsigned char* mrow = mask + ((size_t)b * NS + qt * 128) * NS;

    const int tid = threadIdx.x;
    const int tx = tid & 15;        // k-col group (4 cols)
    const int ty = tid >> 4;        // q-row group (8 rows)

    // ---- load Q tile transposed -> Qs[d][qi]
    {
        int r = tid >> 1;
        int cb = (tid & 1) * 32;
        #pragma unroll
        for (int cc = 0; cc < 32; cc += 4) {
            float4 a = *(const float4*)(qsp + (size_t)r * NDK + cb + cc);
            Qs[(cb + cc + 0) * 128 + r] = a.x;
            Qs[(cb + cc + 1) * 128 + r] = a.y;
            Qs[(cb + cc + 2) * 128 + r] = a.z;
            Qs[(cb + cc + 3) * 128 + r] = a.w;
        }
    }

    float rsum[8];
    #pragma unroll
    for (int i = 0; i < 8; i++) rsum[i] = 0.0f;

    for (int kt = 0; kt < NS; kt += 64) {
        __syncthreads();
        {
            int r = tid & 63;
            int cb = (tid >> 6) * 16;
            #pragma unroll
            for (int cc = 0; cc < 16; cc += 4) {
                float4 a = *(const float4*)(ksp + (size_t)(kt + r) * NDK + cb + cc);
                Ks[(cb + cc + 0) * 64 + r] = a.x;
                Ks[(cb + cc + 1) * 64 + r] = a.y;
                Ks[(cb + cc + 2) * 64 + r] = a.z;
                Ks[(cb + cc + 3) * 64 + r] = a.w;
            }
        }
        __syncthreads();

        float acc[8][4] = {};
        #pragma unroll 2
        for (int d = 0; d < 64; d++) {
            float4 b4 = *(const float4*)&Ks[d * 64 + tx * 4];
            float4 a0 = *(const float4*)&Qs[d * 128 + ty * 8];
            float4 a1 = *(const float4*)&Qs[d * 128 + ty * 8 + 4];
            float av[8] = {a0.x, a0.y, a0.z, a0.w, a1.x, a1.y, a1.z, a1.w};
            float bv[4] = {b4.x, b4.y, b4.z, b4.w};
            #pragma unroll
            for (int i = 0; i < 8; i++)
                #pragma unroll
                for (int j = 0; j < 4; j++)
                    acc[i][j] = fmaf(av[i], bv[j], acc[i][j]);
        }

        #pragma unroll
        for (int i = 0; i < 8; i++) {
            int qi = ty * 8 + i;
            uchar4 m4 = *(const uchar4*)(mrow + (size_t)qi * NS + kt + tx * 4);
            float4 ev;
            ev.x = m4.x ? 0.0f : fexp(acc[i][0]);
            ev.y = m4.y ? 0.0f : fexp(acc[i][1]);
            ev.z = m4.z ? 0.0f : fexp(acc[i][2]);
            ev.w = m4.w ? 0.0f : fexp(acc[i][3]);
            __stcs((float4*)(wrow + (size_t)qi * NS + kt + tx * 4), ev);
            rsum[i] += (ev.x + ev.y) + (ev.z + ev.w);
        }
    }

    // reduce across the 16 tx lanes sharing each row; write 1/sum
    #pragma unroll
    for (int i = 0; i < 8; i++) {
        float v = rsum[i];
        v += __shfl_xor_sync(0xffffffffu, v, 1);
        v += __shfl_xor_sync(0xffffffffu, v, 2);
        v += __shfl_xor_sync(0xffffffffu, v, 4);
        v += __shfl_xor_sync(0xffffffffu, v, 8);
        if (tx == 0) ls[ty * 8 + i] = v;
    }
    __syncthreads();
    if (tid < 128)
        g_rl[((size_t)(b * NH + h) * NS) + qt * 128 + tid] = 1.0f / ls[tid];
}

// ---------------- kernel 2b: PV GEMM, K-tile=32, full-128B-line writeback ---
// grid (NS/64, NH, NB), 256 threads, 64x64 tiles, 4x4 micro.
// Each thread handles 32B-contiguous chunks; 4 threads cover a full 128B
// line per row (no L2 read-modify-write on the 1.07 GB writeback).
#define WPAD 68
__global__ __launch_bounds__(256) void k_pv(float* __restrict__ wgt)
{
    __shared__ float WsT[32][WPAD];   // [k][q-row] transposed weight chunk
    __shared__ float Vs[32][64];      // [k][v]
    __shared__ float rls[64];

    const int qt = blockIdx.x, h = blockIdx.y, b = blockIdx.z;
    const size_t bh = (size_t)(b * NH + h);
    const int m0 = qt * 64;
    float* wrow = wgt + (bh * NS + m0) * NS;
    const float* vsp = g_vs + bh * NS * NDK;

    const int tid = threadIdx.x;
    const int tx = tid & 15, ty = tid >> 4;

    if (tid < 64) rls[tid] = g_rl[bh * NS + m0 + tid];

    // load geometry: W 64 rows x 32 cols, 4 threads/row x 8 floats (32B)
    const int wr = tid >> 2;             // weight row 0..63
    const int wc = (tid & 3) * 8;        // weight col block (8 of 32)
    const int vr = tid >> 3;             // v row 0..31
    const int vc = (tid & 7) * 8;        // v col block (8 of 64)
    __syncthreads();
    const float myrl = rls[wr];

    float acc[4][4] = {};

    for (int kt = 0; kt < NS; kt += 32) {
        {   // W chunk: load, normalize, write back (final), stash transposed
            const float* wp = wrow + (size_t)wr * NS + kt + wc;
            float4 w0 = __ldcs((const float4*)(wp));
            float4 w1 = __ldcs((const float4*)(wp + 4));
            w0.x *= myrl; w0.y *= myrl; w0.z *= myrl; w0.w *= myrl;
            w1.x *= myrl; w1.y *= myrl; w1.z *= myrl; w1.w *= myrl;
            __stcs((float4*)(wrow + (size_t)wr * NS + kt + wc), w0);
            __stcs((float4*)(wrow + (size_t)wr * NS + kt + wc + 4), w1);
            WsT[wc + 0][wr] = w0.x; WsT[wc + 1][wr] = w0.y;
            WsT[wc + 2][wr] = w0.z; WsT[wc + 3][wr] = w0.w;
            WsT[wc + 4][wr] = w1.x; WsT[wc + 5][wr] = w1.y;
            WsT[wc + 6][wr] = w1.z; WsT[wc + 7][wr] = w1.w;
        }
        {   // V chunk [32][64]
            const float* vp = vsp + (size_t)(kt + vr) * NDK + vc;
            *(float4*)&Vs[vr][vc]     = *(const float4*)(vp);
            *(float4*)&Vs[vr][vc + 4] = *(const float4*)(vp + 4);
        }
        __syncthreads();

        #pragma unroll
        for (int kk = 0; kk < 32; kk++) {
            float4 a = *(const float4*)&WsT[kk][ty * 4];
            float4 v = *(const float4*)&Vs[kk][tx * 4];
            float av[4] = {a.x, a.y, a.z, a.w};
            float bv[4] = {v.x, v.y, v.z, v.w};
            #pragma unroll
            for (int i = 0; i < 4; i++)
                #pragma unroll
                for (int j = 0; j < 4; j++)
                    acc[i][j] = fmaf(av[i], bv[j], acc[i][j]);
        }
        __syncthreads();
    }

    // write ctx (already normalized) to g_ctx[b][s][h*64+v]
    #pragma unroll
    for (int i = 0; i < 4; i++) {
        int s = m0 + ty * 4 + i;
        float4 o = make_float4(acc[i][0], acc[i][1], acc[i][2], acc[i][3]);
        *(float4*)&g_ctx[((size_t)b * NS + s) * NDE + h * 64 + tx * 4] = o;
    }
}

// ---------------- kernel 3: out = LN(Q + ctx @ Wo + bo) ---------------------
__global__ __launch_bounds__(256) void k_outln(
    const float* __restrict__ Q, const float* __restrict__ Wo,
    const float* __restrict__ bo, const float* __restrict__ gamma,
    const float* __restrict__ beta, float* __restrict__ out)
{
    const int r0 = blockIdx.x * 16;
    __shared__ float Xs[16][16];
    __shared__ float Wsm[16][512];

    const int tid = threadIdx.x;
    const int row = tid >> 4;           // 0..15
    const int cb = (tid & 15) * 32;     // 32 cols per thread
    const int swz = tid & 7;

    float acc[32];
    #pragma unroll
    for (int j = 0; j < 32; j++) acc[j] = 0.0f;

    for (int k0 = 0; k0 < NDE; k0 += 16) {
        Xs[tid >> 4][tid & 15] = g_ctx[(size_t)(r0 + (tid >> 4)) * NDE + k0 + (tid & 15)];
        {
            int r = tid >> 4;
            int c0 = (tid & 15) * 32;
            #pragma unroll
            for (int cc = 0; cc < 32; cc += 4)
                *(float4*)&Wsm[r][c0 + cc] =
                    *(const float4*)(Wo + (size_t)(k0 + r) * NDE + c0 + cc);
        }
        __syncthreads();
        #pragma unroll 4
        for (int kk = 0; kk < 16; kk++) {
            float x = Xs[row][kk];
            #pragma unroll
            for (int jj = 0; jj < 8; jj++) {
                int j = (jj + swz) & 7;           // bank-swizzled access
                float4 w = *(const float4*)&Wsm[kk][cb + j * 4];
                acc[j * 4 + 0] = fmaf(x, w.x, acc[j * 4 + 0]);
                acc[j * 4 + 1] = fmaf(x, w.y, acc[j * 4 + 1]);
                acc[j * 4 + 2] = fmaf(x, w.z, acc[j * 4 + 2]);
                acc[j * 4 + 3] = fmaf(x, w.w, acc[j * 4 + 3]);
            }
        }
        __syncthreads();
    }

    // add bias + residual, compute LN statistics
    const int gr = r0 + row;
    float s1 = 0.0f, s2 = 0.0f;
    #pragma unroll
    for (int j4 = 0; j4 < 8; j4++) {
        float4 bb = *(const float4*)(bo + cb + j4 * 4);
        float4 rr = *(const float4*)(Q + (size_t)gr * NDE + cb + j4 * 4);
        float* a = &acc[j4 * 4];
        a[0] += bb.x + rr.x; a[1] += bb.y + rr.y;
        a[2] += bb.z + rr.z; a[3] += bb.w + rr.w;
        #pragma unroll
        for (int t = 0; t < 4; t++) { s1 += a[t]; s2 = fmaf(a[t], a[t], s2); }
    }
    // reduce across the 16 threads of this row (contiguous half-warp)
    #pragma unroll
    for (int d = 1; d < 16; d <<= 1) {
        s1 += __shfl_xor_sync(0xffffffffu, s1, d);
        s2 += __shfl_xor_sync(0xffffffffu, s2, d);
    }
    const float mu = s1 * (1.0f / 512.0f);
    const float var = s2 * (1.0f / 512.0f) - mu * mu;
    const float rstd = rsqrtf(var + 1e-5f);

    #pragma unroll
    for (int j4 = 0; j4 < 8; j4++) {
        float4 g = *(const float4*)(gamma + cb + j4 * 4);
        float4 be = *(const float4*)(beta + cb + j4 * 4);
        float4 o;
        o.x = (acc[j4 * 4 + 0] - mu) * rstd * g.x + be.x;
        o.y = (acc[j4 * 4 + 1] - mu) * rstd * g.y + be.y;
        o.z = (acc[j4 * 4 + 2] - mu) * rstd * g.z + be.z;
        o.w = (acc[j4 * 4 + 3] - mu) * rstd * g.w + be.w;
        *(float4*)(out + (size_t)gr * NDE + cb + j4 * 4) = o;
    }
}

// ---------------- launch ----------------------------------------------------
extern "C" void kernel_launch(void* const* d_in, const int* in_sizes, int n_in,
                              void* d_out, int out_size)
{
    const float* Q     = (const float*)d_in[0];
    const float* K     = (const float*)d_in[1];
    const float* V     = (const float*)d_in[2];
    const unsigned char* mask = (const unsigned char*)d_in[3];
    const float* Wq    = (const float*)d_in[4];
    const float* bq    = (const float*)d_in[5];
    const float* Wo    = (const float*)d_in[6];
    const float* bo    = (const float*)d_in[7];
    const float* gamma = (const float*)d_in[8];
    const float* beta  = (const float*)d_in[9];

    float* out = (float*)d_out;                      // [B,S,512] output
    float* wgt = out + (size_t)NB * NS * NDE;        // [B,H,S,S] weights

    static const int QKE_SMEM = 12416 * 4;           // 49664 bytes
    cudaFuncSetAttribute(k_qke, cudaFuncAttributeMaxDynamicSharedMemorySize,
                         QKE_SMEM);

    // 2 dummies + 2 hidden harness prelaunches put k_qke at overall launch
    // #6 = the one ncu's  -s 5 -c 1  captures.
    k_dummy<<<1, 32>>>();
    k_dummy<<<1, 32>>>();

    dim3 gp(NDE / 64, (NB * NS) / 64, 3);
    k_proj<<<gp, 256>>>(Q, K, V, Wq, bq);

    dim3 gq(NS / 128, NH, NB);
    k_qke<<<gq, 256, QKE_SMEM>>>(mask, wgt);

    dim3 gv(NS / 64, NH, NB);
    k_pv<<<gv, 256>>>(wgt);

    k_outln<<<(NB * NS) / 16, 256>>>(Q, Wo, bo, gamma, beta, out);
}

// round 14
// speedup vs baseline: 1.0587x; 1.0587x over previous
#include <cuda_runtime.h>
#include <cstdint>

#define NB 8
#define NS 2048
#define NH 8
#define NDK 64
#define NDE 512

// ---------------- scratch (device globals; no allocations allowed) ----------
__device__ float g_qs[NB * NH * NS * NDK];   // 32 MB, pre-scaled by 1/8
__device__ float g_ks[NB * NH * NS * NDK];   // 32 MB
__device__ float g_vs[NB * NH * NS * NDK];   // 32 MB
__device__ float g_ctx[NB * NS * NDE];       // 32 MB
__device__ float g_rl[NB * NH * NS];         // 512 KB: 1/rowsum per (b,h,s)

// ---------------- fast exp: FFMA-pipe polynomial (MUFU is slow on sm_103a) --
__device__ __forceinline__ float fexp(float x) {
    float y = x * 1.4426950408889634f;          // log2(e)
    y = fminf(fmaxf(y, -120.0f), 120.0f);
    float t = y + 12582912.0f;                  // round-to-nearest-int trick
    float r = t - 12582912.0f;
    float f = y - r;                            // f in [-0.5, 0.5]
    int   ei = __float_as_int(t) - 0x4B400000;  // integer value of r
    float p = 1.3333558146e-3f;
    p = fmaf(p, f, 9.6181291076e-3f);
    p = fmaf(p, f, 5.5504108665e-2f);
    p = fmaf(p, f, 2.4022650696e-1f);
    p = fmaf(p, f, 6.9314718056e-1f);
    p = fmaf(p, f, 1.0f);
    return p * __int_as_float((ei + 127) << 23);
}

// ---------------- dummy: steers ncu's capture (-s 5 -c 1) onto k_pv ---------
// Launch order: [hidden, hidden, dummy, proj, qke, pv, outln] -> #6 = k_pv.
__global__ void k_dummy() {}

// ---------------- kernel 1: projections q_s/k_s/v_s = X @ Wq + bq -----------
__global__ __launch_bounds__(256) void k_proj(
    const float* __restrict__ Q, const float* __restrict__ K,
    const float* __restrict__ V, const float* __restrict__ W,
    const float* __restrict__ bias)
{
    const int which = blockIdx.z;
    const float* X = (which == 0) ? Q : (which == 1) ? K : V;
    float* O = (which == 0) ? g_qs : (which == 1) ? g_ks : g_vs;
    const float scl = (which == 0) ? 0.125f : 1.0f;

    __shared__ float As[16][64];   // [k][m] (transposed)
    __shared__ float Bs[16][64];   // [k][n]

    const int tid = threadIdx.x;
    const int tx = tid & 15, ty = tid >> 4;
    const int m0 = blockIdx.y * 64, n0 = blockIdx.x * 64;

    float acc[4][4] = {};

    for (int k0 = 0; k0 < NDE; k0 += 16) {
        {
            int r = tid >> 2;
            int c = (tid & 3) * 4;
            float4 a = *(const float4*)(X + (size_t)(m0 + r) * NDE + k0 + c);
            As[c + 0][r] = a.x; As[c + 1][r] = a.y;
            As[c + 2][r] = a.z; As[c + 3][r] = a.w;
        }
        {
            int r = tid >> 4;
            int c = (tid & 15) * 4;
            *(float4*)&Bs[r][c] = *(const float4*)(W + (size_t)(k0 + r) * NDE + n0 + c);
        }
        __syncthreads();
        #pragma unroll
        for (int kk = 0; kk < 16; kk++) {
            float4 a = *(const float4*)&As[kk][ty * 4];
            float4 b = *(const float4*)&Bs[kk][tx * 4];
            float av[4] = {a.x, a.y, a.z, a.w};
            float bv[4] = {b.x, b.y, b.z, b.w};
            #pragma unroll
            for (int i = 0; i < 4; i++)
                #pragma unroll
                for (int j = 0; j < 4; j++)
                    acc[i][j] = fmaf(av[i], bv[j], acc[i][j]);
        }
        __syncthreads();
    }

    const int hh = n0 >> 6;                  // whole tile is one head
    float4 bi = *(const float4*)(bias + n0 + tx * 4);
    #pragma unroll
    for (int i = 0; i < 4; i++) {
        int m = m0 + ty * 4 + i;
        int bb = m >> 11;
        int ss = m & 2047;
        float4 o;
        o.x = (acc[i][0] + bi.x) * scl;
        o.y = (acc[i][1] + bi.y) * scl;
        o.z = (acc[i][2] + bi.z) * scl;
        o.w = (acc[i][3] + bi.w) * scl;
        *(float4*)(O + ((size_t)(bb * NH + hh) * NS + ss) * NDK + tx * 4) = o;
    }
}

// ---------------- kernel 2a: QK + exp + unnormalized weight store + rowsums -
// (byte-identical body to R11/R13 — exonerated by its direct profile)
__global__ __launch_bounds__(256) void k_qke(
    const unsigned char* __restrict__ mask, float* __restrict__ wgt)
{
    extern __shared__ float sm[];
    float* Qs = sm;            // [64][128]  (d-major, transposed)
    float* Ks = sm + 8192;     // [64][64]   (d-major, transposed)
    float* ls = sm + 12288;    // [128]

    const int qt = blockIdx.x, h = blockIdx.y, b = blockIdx.z;
    const float* qsp = g_qs + (((size_t)(b * NH + h) * NS) + qt * 128) * NDK;
    const float* ksp = g_ks + ((size_t)(b * NH + h) * NS) * NDK;
    float* wrow = wgt + (((size_t)(b * NH + h) * NS) + qt * 128) * NS;
    const unsigned char* mrow = mask + ((size_t)b * NS + qt * 128) * NS;

    const int tid = threadIdx.x;
    const int tx = tid & 15;        // k-col group (4 cols)
    const int ty = tid >> 4;        // q-row group (8 rows)

    // ---- load Q tile transposed -> Qs[d][qi]
    {
        int r = tid >> 1;
        int cb = (tid & 1) * 32;
        #pragma unroll
        for (int cc = 0; cc < 32; cc += 4) {
            float4 a = *(const float4*)(qsp + (size_t)r * NDK + cb + cc);
            Qs[(cb + cc + 0) * 128 + r] = a.x;
            Qs[(cb + cc + 1) * 128 + r] = a.y;
            Qs[(cb + cc + 2) * 128 + r] = a.z;
            Qs[(cb + cc + 3) * 128 + r] = a.w;
        }
    }

    float rsum[8];
    #pragma unroll
    for (int i = 0; i < 8; i++) rsum[i] = 0.0f;

    for (int kt = 0; kt < NS; kt += 64) {
        __syncthreads();
        {
            int r = tid & 63;
            int cb = (tid >> 6) * 16;
            #pragma unroll
            for (int cc = 0; cc < 16; cc += 4) {
                float4 a = *(const float4*)(ksp + (size_t)(kt + r) * NDK + cb + cc);
                Ks[(cb + cc + 0) * 64 + r] = a.x;
                Ks[(cb + cc + 1) * 64 + r] = a.y;
                Ks[(cb + cc + 2) * 64 + r] = a.z;
                Ks[(cb + cc + 3) * 64 + r] = a.w;
            }
        }
        __syncthreads();

        float acc[8][4] = {};
        #pragma unroll 2
        for (int d = 0; d < 64; d++) {
            float4 b4 = *(const float4*)&Ks[d * 64 + tx * 4];
            float4 a0 = *(const float4*)&Qs[d * 128 + ty * 8];
            float4 a1 = *(const float4*)&Qs[d * 128 + ty * 8 + 4];
            float av[8] = {a0.x, a0.y, a0.z, a0.w, a1.x, a1.y, a1.z, a1.w};
            float bv[4] = {b4.x, b4.y, b4.z, b4.w};
            #pragma unroll
            for (int i = 0; i < 8; i++)
                #pragma unroll
                for (int j = 0; j < 4; j++)
                    acc[i][j] = fmaf(av[i], bv[j], acc[i][j]);
        }

        #pragma unroll
        for (int i = 0; i < 8; i++) {
            int qi = ty * 8 + i;
            uchar4 m4 = *(const uchar4*)(mrow + (size_t)qi * NS + kt + tx * 4);
            float4 ev;
            ev.x = m4.x ? 0.0f : fexp(acc[i][0]);
            ev.y = m4.y ? 0.0f : fexp(acc[i][1]);
            ev.z = m4.z ? 0.0f : fexp(acc[i][2]);
            ev.w = m4.w ? 0.0f : fexp(acc[i][3]);
            __stcs((float4*)(wrow + (size_t)qi * NS + kt + tx * 4), ev);
            rsum[i] += (ev.x + ev.y) + (ev.z + ev.w);
        }
    }

    // reduce across the 16 tx lanes sharing each row; write 1/sum
    #pragma unroll
    for (int i = 0; i < 8; i++) {
        float v = rsum[i];
        v += __shfl_xor_sync(0xffffffffu, v, 1);
        v += __shfl_xor_sync(0xffffffffu, v, 2);
        v += __shfl_xor_sync(0xffffffffu, v, 4);
        v += __shfl_xor_sync(0xffffffffu, v, 8);
        if (tx == 0) ls[ty * 8 + i] = v;
    }
    __syncthreads();
    if (tid < 128)
        g_rl[((size_t)(b * NH + h) * NS) + qt * 128 + tid] = 1.0f / ls[tid];
}

// ---------------- kernel 2b: PV GEMM, K-tile=16, register double-buffered ---
// grid (NS/64, NH, NB), 256 threads, 64x64 tiles, 4x4 micro.
// Next tile's W/V LDGs issue right after the staging barrier and are consumed
// one iteration later -> DRAM latency overlaps the FFMA block instead of
// serializing (the suspected 17 ms pathology).
#define WPAD 68
__global__ __launch_bounds__(256) void k_pv(float* __restrict__ wgt)
{
    __shared__ float WsT[16][WPAD];   // [k][q-row] transposed weight chunk
    __shared__ float Vs[16][64];      // [k][v]
    __shared__ float rls[64];

    const int qt = blockIdx.x, h = blockIdx.y, b = blockIdx.z;
    const size_t bh = (size_t)(b * NH + h);
    const int m0 = qt * 64;
    float* wrow = wgt + (bh * NS + m0) * NS;
    const float* vsp = g_vs + bh * NS * NDK;

    const int tid = threadIdx.x;
    const int tx = tid & 15, ty = tid >> 4;

    if (tid < 64) rls[tid] = g_rl[bh * NS + m0 + tid];

    // load geometry: W 64 rows x 16 cols (4 thr/row x float4), V 16 x 64
    const int wr = tid >> 2;             // weight row 0..63
    const int wc = (tid & 3) * 4;        // weight col block (4 of 16)
    const int vr = tid >> 4;             // v row 0..15
    const int vc = (tid & 15) * 4;       // v col block
    __syncthreads();
    const float myrl = rls[wr];

    float acc[4][4] = {};

    // ---- prologue: prefetch tile 0 into registers
    float4 wreg = __ldcs((const float4*)(wrow + (size_t)wr * NS + wc));
    float4 vreg = *(const float4*)(vsp + (size_t)vr * NDK + vc);

    for (int kt = 0; kt < NS; kt += 16) {
        __syncthreads();   // prev compute done reading smem

        // stage: normalize W in regs, write back final to d_out, stash smem
        wreg.x *= myrl; wreg.y *= myrl; wreg.z *= myrl; wreg.w *= myrl;
        __stcs((float4*)(wrow + (size_t)wr * NS + kt + wc), wreg);
        WsT[wc + 0][wr] = wreg.x; WsT[wc + 1][wr] = wreg.y;
        WsT[wc + 2][wr] = wreg.z; WsT[wc + 3][wr] = wreg.w;
        *(float4*)&Vs[vr][vc] = vreg;
        __syncthreads();

        // prefetch next tile (overlaps the compute below)
        if (kt + 16 < NS) {
            wreg = __ldcs((const float4*)(wrow + (size_t)wr * NS + kt + 16 + wc));
            vreg = *(const float4*)(vsp + (size_t)(kt + 16 + vr) * NDK + vc);
        }

        #pragma unroll
        for (int kk = 0; kk < 16; kk++) {
            float4 a = *(const float4*)&WsT[kk][ty * 4];
            float4 v = *(const float4*)&Vs[kk][tx * 4];
            float av[4] = {a.x, a.y, a.z, a.w};
            float bv[4] = {v.x, v.y, v.z, v.w};
            #pragma unroll
            for (int i = 0; i < 4; i++)
                #pragma unroll
                for (int j = 0; j < 4; j++)
                    acc[i][j] = fmaf(av[i], bv[j], acc[i][j]);
        }
    }

    // write ctx (already normalized) to g_ctx[b][s][h*64+v]
    #pragma unroll
    for (int i = 0; i < 4; i++) {
        int s = m0 + ty * 4 + i;
        float4 o = make_float4(acc[i][0], acc[i][1], acc[i][2], acc[i][3]);
        *(float4*)&g_ctx[((size_t)b * NS + s) * NDE + h * 64 + tx * 4] = o;
    }
}

// ---------------- kernel 3: out = LN(Q + ctx @ Wo + bo) ---------------------
__global__ __launch_bounds__(256) void k_outln(
    const float* __restrict__ Q, const float* __restrict__ Wo,
    const float* __restrict__ bo, const float* __restrict__ gamma,
    const float* __restrict__ beta, float* __restrict__ out)
{
    const int r0 = blockIdx.x * 16;
    __shared__ float Xs[16][16];
    __shared__ float Wsm[16][512];

    const int tid = threadIdx.x;
    const int row = tid >> 4;           // 0..15
    const int cb = (tid & 15) * 32;     // 32 cols per thread
    const int swz = tid & 7;

    float acc[32];
    #pragma unroll
    for (int j = 0; j < 32; j++) acc[j] = 0.0f;

    for (int k0 = 0; k0 < NDE; k0 += 16) {
        Xs[tid >> 4][tid & 15] = g_ctx[(size_t)(r0 + (tid >> 4)) * NDE + k0 + (tid & 15)];
        {
            int r = tid >> 4;
            int c0 = (tid & 15) * 32;
            #pragma unroll
            for (int cc = 0; cc < 32; cc += 4)
                *(float4*)&Wsm[r][c0 + cc] =
                    *(const float4*)(Wo + (size_t)(k0 + r) * NDE + c0 + cc);
        }
        __syncthreads();
        #pragma unroll 4
        for (int kk = 0; kk < 16; kk++) {
            float x = Xs[row][kk];
            #pragma unroll
            for (int jj = 0; jj < 8; jj++) {
                int j = (jj + swz) & 7;           // bank-swizzled access
                float4 w = *(const float4*)&Wsm[kk][cb + j * 4];
                acc[j * 4 + 0] = fmaf(x, w.x, acc[j * 4 + 0]);
                acc[j * 4 + 1] = fmaf(x, w.y, acc[j * 4 + 1]);
                acc[j * 4 + 2] = fmaf(x, w.z, acc[j * 4 + 2]);
                acc[j * 4 + 3] = fmaf(x, w.w, acc[j * 4 + 3]);
            }
        }
        __syncthreads();
    }

    // add bias + residual, compute LN statistics
    const int gr = r0 + row;
    float s1 = 0.0f, s2 = 0.0f;
    #pragma unroll
    for (int j4 = 0; j4 < 8; j4++) {
        float4 bb = *(const float4*)(bo + cb + j4 * 4);
        float4 rr = *(const float4*)(Q + (size_t)gr * NDE + cb + j4 * 4);
        float* a = &acc[j4 * 4];
        a[0] += bb.x + rr.x; a[1] += bb.y + rr.y;
        a[2] += bb.z + rr.z; a[3] += bb.w + rr.w;
        #pragma unroll
        for (int t = 0; t < 4; t++) { s1 += a[t]; s2 = fmaf(a[t], a[t], s2); }
    }
    // reduce across the 16 threads of this row (contiguous half-warp)
    #pragma unroll
    for (int d = 1; d < 16; d <<= 1) {
        s1 += __shfl_xor_sync(0xffffffffu, s1, d);
        s2 += __shfl_xor_sync(0xffffffffu, s2, d);
    }
    const float mu = s1 * (1.0f / 512.0f);
    const float var = s2 * (1.0f / 512.0f) - mu * mu;
    const float rstd = rsqrtf(var + 1e-5f);

    #pragma unroll
    for (int j4 = 0; j4 < 8; j4++) {
        float4 g = *(const float4*)(gamma + cb + j4 * 4);
        float4 be = *(const float4*)(beta + cb + j4 * 4);
        float4 o;
        o.x = (acc[j4 * 4 + 0] - mu) * rstd * g.x + be.x;
        o.y = (acc[j4 * 4 + 1] - mu) * rstd * g.y + be.y;
        o.z = (acc[j4 * 4 + 2] - mu) * rstd * g.z + be.z;
        o.w = (acc[j4 * 4 + 3] - mu) * rstd * g.w + be.w;
        *(float4*)(out + (size_t)gr * NDE + cb + j4 * 4) = o;
    }
}

// ---------------- launch ----------------------------------------------------
extern "C" void kernel_launch(void* const* d_in, const int* in_sizes, int n_in,
                              void* d_out, int out_size)
{
    const float* Q     = (const float*)d_in[0];
    const float* K     = (const float*)d_in[1];
    const float* V     = (const float*)d_in[2];
    const unsigned char* mask = (const unsigned char*)d_in[3];
    const float* Wq    = (const float*)d_in[4];
    const float* bq    = (const float*)d_in[5];
    const float* Wo    = (const float*)d_in[6];
    const float* bo    = (const float*)d_in[7];
    const float* gamma = (const float*)d_in[8];
    const float* beta  = (const float*)d_in[9];

    float* out = (float*)d_out;                      // [B,S,512] output
    float* wgt = out + (size_t)NB * NS * NDE;        // [B,H,S,S] weights

    static const int QKE_SMEM = 12416 * 4;           // 49664 bytes
    cudaFuncSetAttribute(k_qke, cudaFuncAttributeMaxDynamicSharedMemorySize,
                         QKE_SMEM);

    // ONE dummy: [hidden,hidden,dummy,proj,qke,pv,...] -> ncu (-s 5) lands on k_pv
    k_dummy<<<1, 32>>>();

    dim3 gp(NDE / 64, (NB * NS) / 64, 3);
    k_proj<<<gp, 256>>>(Q, K, V, Wq, bq);

    dim3 gq(NS / 128, NH, NB);
    k_qke<<<gq, 256, QKE_SMEM>>>(mask, wgt);

    dim3 gv(NS / 64, NH, NB);
    k_pv<<<gv, 256>>>(wgt);

    k_outln<<<(NB * NS) / 16, 256>>>(Q, Wo, bo, gamma, beta, out);
}

// round 15
// speedup vs baseline: 1.0611x; 1.0022x over previous
#include <cuda_runtime.h>
#include <cuda_bf16.h>
#include <cstdint>

#define NB 8
#define NS 2048
#define NH 8
#define NDK 64
#define NDE 512

// ---------------- scratch (device globals; no allocations allowed) ----------
__device__ __nv_bfloat16 g_qh[NB * NH * NS * NDK];   // 16 MB each
__device__ __nv_bfloat16 g_ql[NB * NH * NS * NDK];
__device__ __nv_bfloat16 g_kh[NB * NH * NS * NDK];
__device__ __nv_bfloat16 g_kl[NB * NH * NS * NDK];
__device__ __nv_bfloat16 g_vh[NB * NH * NS * NDK];
__device__ __nv_bfloat16 g_vl[NB * NH * NS * NDK];
__device__ float g_ctx[NB * NS * NDE];               // 32 MB
__device__ float g_rl[NB * NH * NS];                 // 512 KB

// ---------------- fast exp: FFMA-pipe polynomial ----------------------------
__device__ __forceinline__ float fexp(float x) {
    float y = x * 1.4426950408889634f;
    y = fminf(fmaxf(y, -120.0f), 120.0f);
    float t = y + 12582912.0f;
    float r = t - 12582912.0f;
    float f = y - r;
    int   ei = __float_as_int(t) - 0x4B400000;
    float p = 1.3333558146e-3f;
    p = fmaf(p, f, 9.6181291076e-3f);
    p = fmaf(p, f, 5.5504108665e-2f);
    p = fmaf(p, f, 2.4022650696e-1f);
    p = fmaf(p, f, 6.9314718056e-1f);
    p = fmaf(p, f, 1.0f);
    return p * __int_as_float((ei + 127) << 23);
}

// ---------------- mma / ldmatrix helpers ------------------------------------
#define MMA_BF16(ac, a0, a1, a2, a3, b0, b1)                                   \
    asm volatile(                                                              \
        "mma.sync.aligned.m16n8k16.row.col.f32.bf16.bf16.f32 "                 \
        "{%0,%1,%2,%3},{%4,%5,%6,%7},{%8,%9},{%0,%1,%2,%3};"                   \
        : "+f"((ac)[0]), "+f"((ac)[1]), "+f"((ac)[2]), "+f"((ac)[3])           \
        : "r"(a0), "r"(a1), "r"(a2), "r"(a3), "r"(b0), "r"(b1))

#define LDSM4(r, addr)                                                         \
    asm volatile("ldmatrix.sync.aligned.m8n8.x4.shared.b16 {%0,%1,%2,%3}, [%4];" \
        : "=r"((r)[0]), "=r"((r)[1]), "=r"((r)[2]), "=r"((r)[3]) : "r"(addr))

#define LDSM4T(r, addr)                                                        \
    asm volatile("ldmatrix.sync.aligned.m8n8.x4.trans.shared.b16 {%0,%1,%2,%3}, [%4];" \
        : "=r"((r)[0]), "=r"((r)[1]), "=r"((r)[2]), "=r"((r)[3]) : "r"(addr))

// swizzled element index inside a [rows][64] bf16 plane (128B rows, 16B chunks)
__device__ __forceinline__ int swz(int row, int col) {
    return row * 64 + ((((col >> 3) ^ (row & 7)) << 3) | (col & 7));
}

__device__ __forceinline__ uint32_t smaddr(const void* p) {
    return (uint32_t)__cvta_generic_to_shared(p);
}

// split a float4 into bf16 hi / lo pairs (packed 4 bf16 = uint2)
__device__ __forceinline__ void bsplit4(float4 o, uint2& uh, uint2& ul) {
    __nv_bfloat16 h0 = __float2bfloat16_rn(o.x), h1 = __float2bfloat16_rn(o.y);
    __nv_bfloat16 h2 = __float2bfloat16_rn(o.z), h3 = __float2bfloat16_rn(o.w);
    __nv_bfloat16 l0 = __float2bfloat16_rn(o.x - __bfloat162float(h0));
    __nv_bfloat16 l1 = __float2bfloat16_rn(o.y - __bfloat162float(h1));
    __nv_bfloat16 l2 = __float2bfloat16_rn(o.z - __bfloat162float(h2));
    __nv_bfloat16 l3 = __float2bfloat16_rn(o.w - __bfloat162float(h3));
    __nv_bfloat162 H0; H0.x = h0; H0.y = h1;
    __nv_bfloat162 H1; H1.x = h2; H1.y = h3;
    __nv_bfloat162 L0; L0.x = l0; L0.y = l1;
    __nv_bfloat162 L1; L1.x = l2; L1.y = l3;
    uh.x = *(unsigned*)&H0; uh.y = *(unsigned*)&H1;
    ul.x = *(unsigned*)&L0; ul.y = *(unsigned*)&L1;
}

// ---------------- dummy: steer ncu (-s 5 -c 1) onto k_pv --------------------
__global__ void k_dummy() {}

// ---------------- kernel 1: projections -> bf16 hi/lo planes ----------------
__global__ __launch_bounds__(256) void k_proj(
    const float* __restrict__ Q, const float* __restrict__ K,
    const float* __restrict__ V, const float* __restrict__ W,
    const float* __restrict__ bias)
{
    const int which = blockIdx.z;
    const float* X = (which == 0) ? Q : (which == 1) ? K : V;
    __nv_bfloat16* OH = (which == 0) ? g_qh : (which == 1) ? g_kh : g_vh;
    __nv_bfloat16* OL = (which == 0) ? g_ql : (which == 1) ? g_kl : g_vl;
    const float scl = (which == 0) ? 0.125f : 1.0f;

    __shared__ float As[16][64];
    __shared__ float Bs[16][64];

    const int tid = threadIdx.x;
    const int tx = tid & 15, ty = tid >> 4;
    const int m0 = blockIdx.y * 64, n0 = blockIdx.x * 64;

    float acc[4][4] = {};

    for (int k0 = 0; k0 < NDE; k0 += 16) {
        {
            int r = tid >> 2;
            int c = (tid & 3) * 4;
            float4 a = *(const float4*)(X + (size_t)(m0 + r) * NDE + k0 + c);
            As[c + 0][r] = a.x; As[c + 1][r] = a.y;
            As[c + 2][r] = a.z; As[c + 3][r] = a.w;
        }
        {
            int r = tid >> 4;
            int c = (tid & 15) * 4;
            *(float4*)&Bs[r][c] = *(const float4*)(W + (size_t)(k0 + r) * NDE + n0 + c);
        }
        __syncthreads();
        #pragma unroll
        for (int kk = 0; kk < 16; kk++) {
            float4 a = *(const float4*)&As[kk][ty * 4];
            float4 b = *(const float4*)&Bs[kk][tx * 4];
            float av[4] = {a.x, a.y, a.z, a.w};
            float bv[4] = {b.x, b.y, b.z, b.w};
            #pragma unroll
            for (int i = 0; i < 4; i++)
                #pragma unroll
                for (int j = 0; j < 4; j++)
                    acc[i][j] = fmaf(av[i], bv[j], acc[i][j]);
        }
        __syncthreads();
    }

    const int hh = n0 >> 6;
    float4 bi = *(const float4*)(bias + n0 + tx * 4);
    #pragma unroll
    for (int i = 0; i < 4; i++) {
        int m = m0 + ty * 4 + i;
        int bb = m >> 11;
        int ss = m & 2047;
        float4 o;
        o.x = (acc[i][0] + bi.x) * scl;
        o.y = (acc[i][1] + bi.y) * scl;
        o.z = (acc[i][2] + bi.z) * scl;
        o.w = (acc[i][3] + bi.w) * scl;
        size_t idx = ((size_t)(bb * NH + hh) * NS + ss) * NDK + tx * 4;
        uint2 uh, ul;
        bsplit4(o, uh, ul);
        *(uint2*)&OH[idx] = uh;
        *(uint2*)&OL[idx] = ul;
    }
}

// ---------------- kernel 2a: QK via bf16-split mma + exp + store + rowsums --
// grid (NS/128, NH, NB), 256 thr = 8 warps; warp w owns q-slab [w*16, w*16+16).
// smem (bf16 elems): QH 0, QL 8192, KH 16384, KL 20480; ls floats at byte 49152.
__global__ __launch_bounds__(256, 2) void k_qke(
    const unsigned char* __restrict__ mask, float* __restrict__ wgt)
{
    extern __shared__ char smc[];
    const int QH = 0, QL = 8192, KH = 16384, KL = 20480;
    float* ls = (float*)(smc + 49152);
    const uint32_t smb = smaddr(smc);

    const int qt = blockIdx.x, h = blockIdx.y, b = blockIdx.z;
    const size_t bh = (size_t)(b * NH + h);
    float* wrow = wgt + (bh * NS + qt * 128) * NS;
    const unsigned char* mrow = mask + ((size_t)b * NS + qt * 128) * NS;

    const int tid = threadIdx.x;
    const int lane = tid & 31, w = tid >> 5;
    const int lrow = lane & 15, lsel = lane >> 4;
    const int g = lane >> 2, t = lane & 3;

    // ---- stage Q hi/lo (once): swizzled [128][64]
    {
        int r = tid >> 1;
        int ch0 = (tid & 1) * 4;
        size_t gbase = (bh * NS + qt * 128 + r) * NDK;
        #pragma unroll
        for (int c = 0; c < 4; c++) {
            int ch = ch0 + c;
            *(uint4*)(smc + (QH + swz(r, ch * 8)) * 2) =
                *(const uint4*)(g_qh + gbase + ch * 8);
            *(uint4*)(smc + (QL + swz(r, ch * 8)) * 2) =
                *(const uint4*)(g_ql + gbase + ch * 8);
        }
    }

    float rs0 = 0.0f, rs1 = 0.0f;
    const int arow = w * 16 + lrow;

    for (int kt = 0; kt < NS; kt += 64) {
        __syncthreads();
        {   // stage K hi/lo tile [64 tok][64 d]
            int r = tid >> 2;
            int ch0 = (tid & 3) * 2;
            size_t gbase = (bh * NS + kt + r) * NDK;
            #pragma unroll
            for (int c = 0; c < 2; c++) {
                int ch = ch0 + c;
                *(uint4*)(smc + (KH + swz(r, ch * 8)) * 2) =
                    *(const uint4*)(g_kh + gbase + ch * 8);
                *(uint4*)(smc + (KL + swz(r, ch * 8)) * 2) =
                    *(const uint4*)(g_kl + gbase + ch * 8);
            }
        }
        __syncthreads();

        float acc[8][4] = {};
        #pragma unroll
        for (int ks = 0; ks < 4; ks++) {
            int k0 = ks * 16;
            uint32_t ah[4], al[4];
            LDSM4(ah, smb + (QH + swz(arow, k0 + 8 * lsel)) * 2);
            LDSM4(al, smb + (QL + swz(arow, k0 + 8 * lsel)) * 2);
            #pragma unroll
            for (int nbi = 0; nbi < 4; nbi++) {
                int brow = nbi * 16 + lrow;
                uint32_t bhf[4], blf[4];
                LDSM4(bhf, smb + (KH + swz(brow, k0 + 8 * lsel)) * 2);
                LDSM4(blf, smb + (KL + swz(brow, k0 + 8 * lsel)) * 2);
                // tile nb uses (r0,r2), tile nb+8 uses (r1,r3)
                MMA_BF16(acc[2 * nbi], ah[0], ah[1], ah[2], ah[3], bhf[0], bhf[2]);
                MMA_BF16(acc[2 * nbi], ah[0], ah[1], ah[2], ah[3], blf[0], blf[2]);
                MMA_BF16(acc[2 * nbi], al[0], al[1], al[2], al[3], bhf[0], bhf[2]);
                MMA_BF16(acc[2 * nbi + 1], ah[0], ah[1], ah[2], ah[3], bhf[1], bhf[3]);
                MMA_BF16(acc[2 * nbi + 1], ah[0], ah[1], ah[2], ah[3], blf[1], blf[3]);
                MMA_BF16(acc[2 * nbi + 1], al[0], al[1], al[2], al[3], bhf[1], bhf[3]);
            }
        }

        // ---- epilogue: mask, exp, store unnormalized weights, row sums
        const int qi0 = w * 16 + g;
        float* wr0 = wrow + (size_t)qi0 * NS + kt;
        float* wr1 = wrow + (size_t)(qi0 + 8) * NS + kt;
        const unsigned char* mm0 = mrow + (size_t)qi0 * NS + kt;
        const unsigned char* mm1 = mrow + (size_t)(qi0 + 8) * NS + kt;
        #pragma unroll
        for (int nt = 0; nt < 8; nt++) {
            int c = nt * 8 + 2 * t;
            uchar2 ma = *(const uchar2*)(mm0 + c);
            uchar2 mb = *(const uchar2*)(mm1 + c);
            float e0 = ma.x ? 0.0f : fexp(acc[nt][0]);
            float e1 = ma.y ? 0.0f : fexp(acc[nt][1]);
            float e2 = mb.x ? 0.0f : fexp(acc[nt][2]);
            float e3 = mb.y ? 0.0f : fexp(acc[nt][3]);
            *(float2*)(wr0 + c) = make_float2(e0, e1);
            *(float2*)(wr1 + c) = make_float2(e2, e3);
            rs0 += e0 + e1;
            rs1 += e2 + e3;
        }
    }

    // quad-reduce (lanes sharing a row differ only in t)
    rs0 += __shfl_xor_sync(0xffffffffu, rs0, 1);
    rs0 += __shfl_xor_sync(0xffffffffu, rs0, 2);
    rs1 += __shfl_xor_sync(0xffffffffu, rs1, 1);
    rs1 += __shfl_xor_sync(0xffffffffu, rs1, 2);
    if (t == 0) {
        ls[w * 16 + g] = rs0;
        ls[w * 16 + g + 8] = rs1;
    }
    __syncthreads();
    if (tid < 128)
        g_rl[bh * NS + qt * 128 + tid] = 1.0f / ls[tid];
}

// ---------------- kernel 2b: PV via bf16-split mma + normalize writeback ----
// grid (NS/128, NH, NB). Reads unnormalized W (fp32), scales by 1/rowsum,
// writes final weights to d_out once, splits to bf16 for the mma.
// smem: WH 0, WL 8192, VH 16384, VL 20480 (bf16 elems); rls at byte 49152.
__global__ __launch_bounds__(256, 2) void k_pv(float* __restrict__ wgt)
{
    extern __shared__ char smc[];
    const int WH = 0, WL = 8192, VH = 16384, VL = 20480;
    float* rls = (float*)(smc + 49152);
    const uint32_t smb = smaddr(smc);

    const int qt = blockIdx.x, h = blockIdx.y, b = blockIdx.z;
    const size_t bh = (size_t)(b * NH + h);
    float* wrow = wgt + (bh * NS + qt * 128) * NS;

    const int tid = threadIdx.x;
    const int lane = tid & 31, w = tid >> 5;
    const int lrow = lane & 15, lsel = lane >> 4;
    const int g = lane >> 2, t = lane & 3;

    if (tid < 128)
        rls[tid] = g_rl[bh * NS + qt * 128 + tid];

    float acc[8][4] = {};
    const int arow = w * 16 + lrow;
    const int wr = tid >> 1;              // staged W row 0..127
    const int wc0 = (tid & 1) * 32;       // 32 cols per thread

    for (int kc = 0; kc < NS; kc += 64) {
        __syncthreads();   // prev compute done; rls visible (1st iter)

        {   // stage W: load fp32, normalize, write back final, split to bf16
            const float myrl = rls[wr];
            float4 f[8];
            const float4* src = (const float4*)(wrow + (size_t)wr * NS + kc + wc0);
            #pragma unroll
            for (int i = 0; i < 8; i++) {
                f[i] = __ldcs(src + i);
                f[i].x *= myrl; f[i].y *= myrl; f[i].z *= myrl; f[i].w *= myrl;
            }
            float4* dst = (float4*)(wrow + (size_t)wr * NS + kc + wc0);
            #pragma unroll
            for (int i = 0; i < 8; i++) __stcs(dst + i, f[i]);
            #pragma unroll
            for (int cc = 0; cc < 4; cc++) {
                uint2 h0, l0, h1, l1;
                bsplit4(f[2 * cc], h0, l0);
                bsplit4(f[2 * cc + 1], h1, l1);
                uint4 Hv = make_uint4(h0.x, h0.y, h1.x, h1.y);
                uint4 Lv = make_uint4(l0.x, l0.y, l1.x, l1.y);
                *(uint4*)(smc + (WH + swz(wr, wc0 + cc * 8)) * 2) = Hv;
                *(uint4*)(smc + (WL + swz(wr, wc0 + cc * 8)) * 2) = Lv;
            }
        }
        {   // stage V hi/lo tile [64 tok][64 v]
            int r = tid >> 2;
            int ch0 = (tid & 3) * 2;
            size_t gbase = (bh * NS + kc + r) * NDK;
            #pragma unroll
            for (int c = 0; c < 2; c++) {
                int ch = ch0 + c;
                *(uint4*)(smc + (VH + swz(r, ch * 8)) * 2) =
                    *(const uint4*)(g_vh + gbase + ch * 8);
                *(uint4*)(smc + (VL + swz(r, ch * 8)) * 2) =
                    *(const uint4*)(g_vl + gbase + ch * 8);
            }
        }
        __syncthreads();

        #pragma unroll
        for (int ks = 0; ks < 4; ks++) {
            int k0 = ks * 16;
            uint32_t ah[4], al[4];
            LDSM4(ah, smb + (WH + swz(arow, k0 + 8 * lsel)) * 2);
            LDSM4(al, smb + (WL + swz(arow, k0 + 8 * lsel)) * 2);
            #pragma unroll
            for (int nbi = 0; nbi < 4; nbi++) {
                int nb = nbi * 16;
                int vrow = k0 + lrow;
                uint32_t bhf[4], blf[4];
                LDSM4T(bhf, smb + (VH + swz(vrow, nb + 8 * lsel)) * 2);
                LDSM4T(blf, smb + (VL + swz(vrow, nb + 8 * lsel)) * 2);
                // trans: tile nb uses (r0,r1), tile nb+8 uses (r2,r3)
                MMA_BF16(acc[2 * nbi], ah[0], ah[1], ah[2], ah[3], bhf[0], bhf[1]);
                MMA_BF16(acc[2 * nbi], ah[0], ah[1], ah[2], ah[3], blf[0], blf[1]);
                MMA_BF16(acc[2 * nbi], al[0], al[1], al[2], al[3], bhf[0], bhf[1]);
                MMA_BF16(acc[2 * nbi + 1], ah[0], ah[1], ah[2], ah[3], bhf[2], bhf[3]);
                MMA_BF16(acc[2 * nbi + 1], ah[0], ah[1], ah[2], ah[3], blf[2], blf[3]);
                MMA_BF16(acc[2 * nbi + 1], al[0], al[1], al[2], al[3], bhf[2], bhf[3]);
            }
        }
    }

    // ---- write ctx (already normalized) to g_ctx[b][s][h*64+v]
    const int qi0 = qt * 128 + w * 16 + g;
    #pragma unroll
    for (int nt = 0; nt < 8; nt++) {
        int c = nt * 8 + 2 * t;
        *(float2*)&g_ctx[((size_t)b * NS + qi0) * NDE + h * 64 + c] =
            make_float2(acc[nt][0], acc[nt][1]);
        *(float2*)&g_ctx[((size_t)b * NS + qi0 + 8) * NDE + h * 64 + c] =
            make_float2(acc[nt][2], acc[nt][3]);
    }
}

// ---------------- kernel 3: out = LN(Q + ctx @ Wo + bo) ---------------------
__global__ __launch_bounds__(256) void k_outln(
    const float* __restrict__ Q, const float* __restrict__ Wo,
    const float* __restrict__ bo, const float* __restrict__ gamma,
    const float* __restrict__ beta, float* __restrict__ out)
{
    const int r0 = blockIdx.x * 16;
    __shared__ float Xs[16][16];
    __shared__ float Wsm[16][512];

    const int tid = threadIdx.x;
    const int row = tid >> 4;
    const int cb = (tid & 15) * 32;
    const int swzp = tid & 7;

    float acc[32];
    #pragma unroll
    for (int j = 0; j < 32; j++) acc[j] = 0.0f;

    for (int k0 = 0; k0 < NDE; k0 += 16) {
        Xs[tid >> 4][tid & 15] = g_ctx[(size_t)(r0 + (tid >> 4)) * NDE + k0 + (tid & 15)];
        {
            int r = tid >> 4;
            int c0 = (tid & 15) * 32;
            #pragma unroll
            for (int cc = 0; cc < 32; cc += 4)
                *(float4*)&Wsm[r][c0 + cc] =
                    *(const float4*)(Wo + (size_t)(k0 + r) * NDE + c0 + cc);
        }
        __syncthreads();
        #pragma unroll 4
        for (int kk = 0; kk < 16; kk++) {
            float x = Xs[row][kk];
            #pragma unroll
            for (int jj = 0; jj < 8; jj++) {
                int j = (jj + swzp) & 7;
                float4 ww = *(const float4*)&Wsm[kk][cb + j * 4];
                acc[j * 4 + 0] = fmaf(x, ww.x, acc[j * 4 + 0]);
                acc[j * 4 + 1] = fmaf(x, ww.y, acc[j * 4 + 1]);
                acc[j * 4 + 2] = fmaf(x, ww.z, acc[j * 4 + 2]);
                acc[j * 4 + 3] = fmaf(x, ww.w, acc[j * 4 + 3]);
            }
        }
        __syncthreads();
    }

    const int gr = r0 + row;
    float s1 = 0.0f, s2 = 0.0f;
    #pragma unroll
    for (int j4 = 0; j4 < 8; j4++) {
        float4 bb = *(const float4*)(bo + cb + j4 * 4);
        float4 rr = *(const float4*)(Q + (size_t)gr * NDE + cb + j4 * 4);
        float* a = &acc[j4 * 4];
        a[0] += bb.x + rr.x; a[1] += bb.y + rr.y;
        a[2] += bb.z + rr.z; a[3] += bb.w + rr.w;
        #pragma unroll
        for (int tt = 0; tt < 4; tt++) { s1 += a[tt]; s2 = fmaf(a[tt], a[tt], s2); }
    }
    #pragma unroll
    for (int d = 1; d < 16; d <<= 1) {
        s1 += __shfl_xor_sync(0xffffffffu, s1, d);
        s2 += __shfl_xor_sync(0xffffffffu, s2, d);
    }
    const float mu = s1 * (1.0f / 512.0f);
    const float var = s2 * (1.0f / 512.0f) - mu * mu;
    const float rstd = rsqrtf(var + 1e-5f);

    #pragma unroll
    for (int j4 = 0; j4 < 8; j4++) {
        float4 gm = *(const float4*)(gamma + cb + j4 * 4);
        float4 be = *(const float4*)(beta + cb + j4 * 4);
        float4 o;
        o.x = (acc[j4 * 4 + 0] - mu) * rstd * gm.x + be.x;
        o.y = (acc[j4 * 4 + 1] - mu) * rstd * gm.y + be.y;
        o.z = (acc[j4 * 4 + 2] - mu) * rstd * gm.z + be.z;
        o.w = (acc[j4 * 4 + 3] - mu) * rstd * gm.w + be.w;
        *(float4*)(out + (size_t)gr * NDE + cb + j4 * 4) = o;
    }
}

// ---------------- launch ----------------------------------------------------
extern "C" void kernel_launch(void* const* d_in, const int* in_sizes, int n_in,
                              void* d_out, int out_size)
{
    const float* Q     = (const float*)d_in[0];
    const float* K     = (const float*)d_in[1];
    const float* V     = (const float*)d_in[2];
    const unsigned char* mask = (const unsigned char*)d_in[3];
    const float* Wq    = (const float*)d_in[4];
    const float* bq    = (const float*)d_in[5];
    const float* Wo    = (const float*)d_in[6];
    const float* bo    = (const float*)d_in[7];
    const float* gamma = (const float*)d_in[8];
    const float* beta  = (const float*)d_in[9];

    float* out = (float*)d_out;                      // [B,S,512] output
    float* wgt = out + (size_t)NB * NS * NDE;        // [B,H,S,S] weights

    static const int MMA_SMEM = 49664;               // 48KB bf16 planes + 512B
    cudaFuncSetAttribute(k_qke, cudaFuncAttributeMaxDynamicSharedMemorySize,
                         MMA_SMEM);
    cudaFuncSetAttribute(k_pv, cudaFuncAttributeMaxDynamicSharedMemorySize,
                         MMA_SMEM);

    // one dummy: [hidden,hidden,dummy,proj,qke,pv,...] -> ncu lands on k_pv
    k_dummy<<<1, 32>>>();

    dim3 gp(NDE / 64, (NB * NS) / 64, 3);
    k_proj<<<gp, 256>>>(Q, K, V, Wq, bq);

    dim3 ga(NS / 128, NH, NB);
    k_qke<<<ga, 256, MMA_SMEM>>>(mask, wgt);
    k_pv<<<ga, 256, MMA_SMEM>>>(wgt);

    k_outln<<<(NB * NS) / 16, 256>>>(Q, Wo, bo, gamma, beta, out);
}